// round 17
// baseline (speedup 1.0000x reference)
#include <cuda_runtime.h>
#include <cstdint>

#define N_ROUNDS 64
#define HID      256
#define NBATCH   8192
#define KW       64            // 256 k / 4 per int8x4 word
#define TILE_R   32            // batch rows per CTA
#define NTHREADS 384           // 12 warps: 8 tensor + 4 dp4a
#define NBLOCKS  (NBATCH / TILE_R)   // 256  -> 2 CTAs/SM

#define XS_STRIDE 40           // padded word stride for x (bank = (8w+row)%32)
#define XS_WORDS  (KW * XS_STRIDE)          // 2560
#define MS_STRIDE 264          // padded word stride for M
#define MS_WORDS  (KW * MS_STRIDE)          // 16896
#define MS_BYTES  (MS_WORDS * 4)            // 67584

// split: tensor warps 0..7 -> IMMA cols [0,128) (16 cols each, NSUB=2, all 32 rows)
//        dp4a  warps 8..11 -> cols [128,256) (32 cols each, 1 row per lane)
#define NSUB     2
#define C_D      128
#define DCOLS    32

// smem word offsets (single M buffer)
#define W_MBAR 0
#define W_XS   8
#define W_MS   (W_XS + 2 * XS_WORDS)        // 5128 -> byte 20512 (16B aligned)
#define SMEM_WORDS (W_MS + MS_WORDS)        // 22024 -> 88096 B per CTA

static __device__ __align__(16) uint32_t g_Mp[N_ROUNDS * MS_WORDS];   // ~4.3 MB

__global__ void pack_matrices_kernel(const float* __restrict__ mats) {
    int idx = blockIdx.x * blockDim.x + threadIdx.x;   // 64*256*64 threads
    int w = idx & (KW - 1);
    int h = (idx >> 6) & (HID - 1);
    int r = idx >> 14;
    const float4 v = *reinterpret_cast<const float4*>(
        mats + ((size_t)(r * HID + h) * HID + (w << 2)));
    uint32_t p = ((uint32_t)((int)v.x) & 0xFFu)
               | (((uint32_t)((int)v.y) & 0xFFu) << 8)
               | (((uint32_t)((int)v.z) & 0xFFu) << 16)
               | (((uint32_t)((int)v.w) & 0xFFu) << 24);
    g_Mp[(size_t)r * MS_WORDS + w * MS_STRIDE + h] = p;
}

__device__ __forceinline__ uint32_t smem_u32(const void* p) {
    uint32_t a;
    asm("{ .reg .u64 t; cvta.to.shared.u64 t, %1; cvt.u32.u64 %0, t; }" : "=r"(a) : "l"(p));
    return a;
}
__device__ __forceinline__ void imma(int* c, const uint32_t* a, const uint32_t* b) {
    asm volatile(
        "mma.sync.aligned.m16n8k32.row.col.s32.s8.s8.s32 "
        "{%0,%1,%2,%3}, {%4,%5,%6,%7}, {%8,%9}, {%0,%1,%2,%3};"
        : "+r"(c[0]), "+r"(c[1]), "+r"(c[2]), "+r"(c[3])
        : "r"(a[0]), "r"(a[1]), "r"(a[2]), "r"(a[3]), "r"(b[0]), "r"(b[1]));
}

#define MBAR_INIT(a, c)  asm volatile("mbarrier.init.shared.b64 [%0], %1;" :: "r"(a), "r"(c) : "memory")
#define MBAR_EXPECT_TX(a, b) asm volatile("mbarrier.arrive.expect_tx.shared.b64 _, [%0], %1;" :: "r"(a), "r"(b) : "memory")
#define MBAR_WAIT(a, ph) do { \
    uint32_t _m = (a), _p = (ph), _d; \
    asm volatile("{ .reg .pred p; mbarrier.try_wait.parity.acquire.cta.shared::cta.b64 p, [%1], %2; selp.b32 %0,1,0,p; }" \
        : "=r"(_d) : "r"(_m), "r"(_p) : "memory"); \
    if (!_d) { \
        asm volatile("{ .reg .pred P1; WL%=: mbarrier.try_wait.parity.acquire.cta.shared::cta.b64 P1, [%0], %1, 0x989680; @P1 bra.uni WD%=; bra.uni WL%=; WD%=: }" \
            :: "r"(_m), "r"(_p) : "memory"); \
    } } while (0)
#define BULK_G2S(dst, src, bytes, mbar) \
    asm volatile("cp.async.bulk.shared::cluster.global.mbarrier::complete_tx::bytes [%0], [%1], %2, [%3];" \
        :: "r"(dst), "l"(src), "r"(bytes), "r"(mbar) : "memory")

__global__ __launch_bounds__(NTHREADS, 2) void tenshash_kernel(
    const int*   __restrict__ nonces,   // [8192, 32]
    const float* __restrict__ noise,    // [8192, 64, 256]; nonzero only round 0
    float*       __restrict__ out)      // [8192, 256]
{
    extern __shared__ uint32_t smem[];
    const uint32_t sb = smem_u32(smem);
    const uint32_t mbar = sb + W_MBAR * 4;
    const uint32_t ms_addr = sb + W_MS * 4;

    const int tid  = threadIdx.x;
    const int lane = tid & 31;
    const int wid  = tid >> 5;
    const int b0   = blockIdx.x * TILE_R;

    if (tid == 0) MBAR_INIT(mbar, 1);

    // ---- init packed x0 (buffer 0) from nonce bits ----
    for (int i = tid; i < TILE_R * KW; i += NTHREADS) {
        int w   = i & (KW - 1);
        int row = i >> 6;
        int v   = nonces[(b0 + row) * 32 + (w >> 1)];
        int j0  = (w & 1) << 2;
        uint32_t p = ((uint32_t)((v >> j0) & 1))
                   | ((uint32_t)((v >> (j0 + 1)) & 1) << 8)
                   | ((uint32_t)((v >> (j0 + 2)) & 1) << 16)
                   | ((uint32_t)((v >> (j0 + 3)) & 1) << 24);
        smem[W_XS + w * XS_STRIDE + row] = p;
    }
    __syncthreads();   // mbar init + xs visible

    // round-0 matrix copy
    if (tid == 0) {
        MBAR_EXPECT_TX(mbar, MS_BYTES);
        BULK_G2S(ms_addr, (const void*)g_Mp, MS_BYTES, mbar);
    }

    const bool is_tensor = (wid < 8);
    const int g  = lane >> 2;
    const int tg = lane & 3;
    const int n0b = wid * (NSUB * 8);        // IMMA col base: 0,16,...,112
    const int dwid = wid - 8;
    const int c0d  = C_D + dwid * DCOLS;     // 128,160,192,224

    int c[2][NSUB][4];
    if (is_tensor) {
        #pragma unroll
        for (int mi = 0; mi < 2; mi++)
            #pragma unroll
            for (int ni = 0; ni < NSUB; ni++)
                #pragma unroll
                for (int t = 0; t < 4; t++) c[mi][ni][t] = 0;
    }

    for (int r = 0; r < N_ROUNDS; r++) {
        const uint32_t* xs  = smem + W_XS + (r & 1) * XS_WORDS;
        uint32_t*       xsn = smem + W_XS + ((r + 1) & 1) * XS_WORDS;
        const uint32_t* ms  = smem + W_MS;

        // wait for this round's matrix (copy issued after previous round's barrier)
        MBAR_WAIT(mbar, (uint32_t)(r & 1));

        if (is_tensor) {
            // ---- IMMA: all 32 rows x 16 cols of [0,128) ----
            #pragma unroll
            for (int kc = 0; kc < 8; kc++) {
                const int wb = kc * 8;
                uint32_t a[2][4], b[NSUB][2];
                #pragma unroll
                for (int mi = 0; mi < 2; mi++) {
                    const int rr = mi * 16 + g;
                    a[mi][0] = xs[(wb + tg) * XS_STRIDE + rr];
                    a[mi][1] = xs[(wb + tg) * XS_STRIDE + rr + 8];
                    a[mi][2] = xs[(wb + 4 + tg) * XS_STRIDE + rr];
                    a[mi][3] = xs[(wb + 4 + tg) * XS_STRIDE + rr + 8];
                }
                #pragma unroll
                for (int ni = 0; ni < NSUB; ni++) {
                    const int n = n0b + ni * 8 + g;
                    b[ni][0] = ms[(wb + tg) * MS_STRIDE + n];
                    b[ni][1] = ms[(wb + 4 + tg) * MS_STRIDE + n];
                }
                #pragma unroll
                for (int mi = 0; mi < 2; mi++)
                    #pragma unroll
                    for (int ni = 0; ni < NSUB; ni++)
                        imma(c[mi][ni], a[mi], b[ni]);
            }

            // ---- IMMA epilogue: (+noise r0) mod 2, repack, store ----
            #pragma unroll
            for (int mi = 0; mi < 2; mi++) {
                #pragma unroll
                for (int ni = 0; ni < NSUB; ni++) {
                    int* cc = c[mi][ni];
                    const int rowA = mi * 16 + g;
                    const int colA = n0b + ni * 8 + tg * 2;
                    if (r == 0) {
                        const float* np  = noise + (size_t)(b0 + rowA) * (N_ROUNDS * HID) + colA;
                        const float* np8 = noise + (size_t)(b0 + rowA + 8) * (N_ROUNDS * HID) + colA;
                        cc[0] += (int)np[0];  cc[1] += (int)np[1];
                        cc[2] += (int)np8[0]; cc[3] += (int)np8[1];
                    }
                    int v0 = cc[0] % 2, v1 = cc[1] % 2, v2 = cc[2] % 2, v3 = cc[3] % 2;
                    cc[0] = cc[1] = cc[2] = cc[3] = 0;
                    if (r + 1 < N_ROUNDS) {
                        uint32_t plo = ((uint32_t)v0 & 0xFFu) | (((uint32_t)v1 & 0xFFu) << 8);
                        uint32_t phi = ((uint32_t)v2 & 0xFFu) | (((uint32_t)v3 & 0xFFu) << 8);
                        uint32_t qlo = __shfl_xor_sync(0xFFFFFFFFu, plo, 1);
                        uint32_t qhi = __shfl_xor_sync(0xFFFFFFFFu, phi, 1);
                        if ((tg & 1) == 0) {
                            const int w = ((n0b + ni * 8) >> 2) + (tg >> 1);
                            xsn[w * XS_STRIDE + rowA]     = (plo & 0xFFFFu) | (qlo << 16);
                            xsn[w * XS_STRIDE + rowA + 8] = (phi & 0xFFFFu) | (qhi << 16);
                        }
                    } else {
                        float* o  = out + (size_t)(b0 + rowA) * HID + colA;
                        float* o8 = out + (size_t)(b0 + rowA + 8) * HID + colA;
                        o[0]  = (float)v0;  o[1]  = (float)v1;
                        o8[0] = (float)v2;  o8[1] = (float)v3;
                    }
                }
            }
        } else {
            // ---- dp4a path: 1 row/lane x 32 cols, cols [128,256) ----
            int acc[DCOLS];
            #pragma unroll
            for (int j = 0; j < DCOLS; j++) acc[j] = 0;

            #pragma unroll 4
            for (int w = 0; w < KW; w++) {
                uint32_t xv = xs[w * XS_STRIDE + lane];
                const uint4* mp = reinterpret_cast<const uint4*>(&ms[w * MS_STRIDE + c0d]);
                #pragma unroll
                for (int q = 0; q < DCOLS / 4; q++) {
                    uint4 m = mp[q];
                    acc[q * 4 + 0] = __dp4a((int)xv, (int)m.x, acc[q * 4 + 0]);
                    acc[q * 4 + 1] = __dp4a((int)xv, (int)m.y, acc[q * 4 + 1]);
                    acc[q * 4 + 2] = __dp4a((int)xv, (int)m.z, acc[q * 4 + 2]);
                    acc[q * 4 + 3] = __dp4a((int)xv, (int)m.w, acc[q * 4 + 3]);
                }
            }

            if (r == 0) {
                const float* np = noise + (size_t)(b0 + lane) * (N_ROUNDS * HID) + c0d;
                #pragma unroll
                for (int j = 0; j < DCOLS; j++) acc[j] += (int)np[j];
            }

            if (r + 1 < N_ROUNDS) {
                #pragma unroll
                for (int jw = 0; jw < DCOLS / 4; jw++) {
                    uint32_t pk = 0;
                    #pragma unroll
                    for (int t = 0; t < 4; t++)
                        pk |= ((uint32_t)(acc[jw * 4 + t] % 2) & 0xFFu) << (t * 8);
                    const int w = (c0d >> 2) + jw;
                    xsn[w * XS_STRIDE + lane] = pk;
                }
            } else {
                float* o = out + (size_t)(b0 + lane) * HID + c0d;
                #pragma unroll
                for (int j = 0; j < DCOLS; j++) o[j] = (float)(acc[j] % 2);
            }
        }

        __syncthreads();   // all xsn writes + ms reads complete

        // single-buffer refill for next round (safe: all readers passed barrier);
        // its latency is covered by the co-resident CTA on this SM
        if (tid == 0 && r + 1 < N_ROUNDS) {
            MBAR_EXPECT_TX(mbar, MS_BYTES);
            BULK_G2S(ms_addr, (const void*)(g_Mp + (size_t)(r + 1) * MS_WORDS),
                     MS_BYTES, mbar);
        }
    }
}

extern "C" void kernel_launch(void* const* d_in, const int* in_sizes, int n_in,
                              void* d_out, int out_size) {
    const int*   nonces = (const int*)d_in[0];
    const float* mats   = (const float*)d_in[1];
    const float* noise  = (const float*)d_in[2];
    float*       out    = (float*)d_out;

    const int smem_bytes = SMEM_WORDS * 4;   // 88096 per CTA (2 CTAs/SM)
    cudaFuncSetAttribute(tenshash_kernel,
                         cudaFuncAttributeMaxDynamicSharedMemorySize, smem_bytes);

    pack_matrices_kernel<<<(N_ROUNDS * HID * KW) / 256, 256>>>(mats);
    tenshash_kernel<<<NBLOCKS, NTHREADS, smem_bytes>>>(nonces, noise, out);
}